// round 1
// baseline (speedup 1.0000x reference)
#include <cuda_runtime.h>
#include <math.h>

#define Bb 4
#define Nn 256
#define Tt 128
#define Ff 64
#define Kk 8
#define Hh 256
#define Ee 8
#define RR (Bb*Nn*Tt)   /* 131072 rows (b,n,t) */

// Scratch (allocation-free: __device__ globals)
__device__ float g_h[(size_t)RR*Hh];      // h = x@in_w+b, layout (b,n,t,h)  134MB
__device__ float g_S[(size_t)RR*Hh];      // lag-aggregated, layout (b,n,t,h) 134MB
__device__ float g_An[Kk*Nn*Nn];          // row-normalized A  2MB
__device__ float g_ctxp[Bb*64*Ff];        // ctx partial sums
__device__ float g_ctx[Bb*Ff];
__device__ float g_alpha[Bb*Kk];

__device__ __forceinline__ float gelu_f(float x){
    return 0.5f*x*(1.0f + erff(x*0.7071067811865476f));
}

// ---------------- A normalization: one block per (k,i) row ----------------
__global__ void norm_A_kernel(const float* __restrict__ A_list){
    int row = blockIdx.x;          // 0..K*N-1
    int j = threadIdx.x;           // 0..255
    float v = A_list[(size_t)row*Nn + j];
    __shared__ float red[256];
    red[j] = v; __syncthreads();
    #pragma unroll
    for (int s=128; s>0; s>>=1){ if (j<s) red[j]+=red[j+s]; __syncthreads(); }
    float denom = fmaxf(red[0], 1e-8f);
    g_An[(size_t)row*Nn + j] = v/denom;
}

// ---------------- ctx = mean over (n,t) of x : two stage ----------------
__global__ void ctx1_kernel(const float* __restrict__ x){
    int c = blockIdx.x;            // chunk 0..63 over nt
    int b = blockIdx.y;
    int f = threadIdx.x & 63;
    int part = threadIdx.x >> 6;   // 0..3
    const float* xb = x + (size_t)b*Nn*Tt*Ff;
    int start = c*512 + part*128;
    float acc = 0.f;
    for (int nt=start; nt<start+128; nt++) acc += xb[(size_t)nt*Ff + f];
    __shared__ float red[256];
    red[threadIdx.x] = acc; __syncthreads();
    if (part==0)
        g_ctxp[((size_t)b*64 + c)*Ff + f] = red[f]+red[64+f]+red[128+f]+red[192+f];
}

__global__ void ctx2_kernel(){
    int b = blockIdx.x; int f = threadIdx.x;
    float s = 0.f;
    for (int c=0;c<64;c++) s += g_ctxp[((size_t)b*64 + c)*Ff + f];
    g_ctx[b*Ff + f] = s * (1.0f/(Nn*Tt));
}

// ---------------- gating MLP -> alpha[b,k] ----------------
__global__ void alpha_kernel(const float* __restrict__ lag_embed,
                             const float* __restrict__ ctx_w1, const float* __restrict__ ctx_b1,
                             const float* __restrict__ ctx_w2, const float* __restrict__ ctx_b2,
                             const float* __restrict__ gate_w1, const float* __restrict__ gate_b1,
                             const float* __restrict__ gate_w2, const float* __restrict__ gate_b2){
    int tid = threadIdx.x;
    if (tid >= Bb*Kk) return;
    int b = tid / Kk, k = tid % Kk;
    float t1[Ee];
    #pragma unroll
    for (int e=0;e<Ee;e++){
        float s = ctx_b1[e];
        for (int f=0;f<Ff;f++) s += g_ctx[b*Ff+f]*ctx_w1[f*Ee+e];
        t1[e] = gelu_f(s);
    }
    float cf[Ee];
    #pragma unroll
    for (int e2=0;e2<Ee;e2++){
        float s = ctx_b2[e2];
        for (int e=0;e<Ee;e++) s += t1[e]*ctx_w2[e*Ee+e2];
        cf[e2] = s;
    }
    float gi[2*Ee];
    #pragma unroll
    for (int e=0;e<Ee;e++){ gi[e]=lag_embed[k*Ee+e]; gi[Ee+e]=cf[e]; }
    float g1[Ee];
    #pragma unroll
    for (int e=0;e<Ee;e++){
        float s = gate_b1[e];
        for (int i=0;i<2*Ee;i++) s += gi[i]*gate_w1[i*Ee+e];
        g1[e] = gelu_f(s);
    }
    float s = gate_b2[0];
    #pragma unroll
    for (int e=0;e<Ee;e++) s += g1[e]*gate_w2[e];
    g_alpha[b*Kk + k] = 1.0f/(1.0f + expf(-s));
}

// ---------------- GEMM1: h = x @ in_w + in_b  (131072x64 @ 64x256) ----------------
// BM=64, BN=64, K=64 (full), 256 threads, 4x4 micro-tile
__global__ void __launch_bounds__(256) gemm1_kernel(const float* __restrict__ x,
                                                    const float* __restrict__ in_w,
                                                    const float* __restrict__ in_b){
    __shared__ float Ast[64*68];   // [kk][ii], padded
    __shared__ float Bs[64*64];    // [kk][cc]
    int r0 = blockIdx.y * 64;
    int c0 = blockIdx.x * 64;
    int tid = threadIdx.x;
    int tx = tid & 15, ty = tid >> 4;
    #pragma unroll
    for (int l=0;l<16;l++){
        int idx = tid + l*256;
        int kk = idx & 63, ii = idx >> 6;
        Ast[kk*68 + ii] = x[(size_t)(r0+ii)*Ff + kk];
    }
    #pragma unroll
    for (int l=0;l<16;l++){
        int idx = tid + l*256;
        int cc = idx & 63, kk = idx >> 6;
        Bs[kk*64 + cc] = in_w[(size_t)kk*Hh + c0 + cc];
    }
    __syncthreads();
    float acc[4][4] = {};
    #pragma unroll 8
    for (int kk=0; kk<64; kk++){
        float4 a = *(const float4*)&Ast[kk*68 + ty*4];
        float4 w = *(const float4*)&Bs[kk*64 + tx*4];
        float av[4]={a.x,a.y,a.z,a.w}, bv[4]={w.x,w.y,w.z,w.w};
        #pragma unroll
        for (int i=0;i<4;i++)
            #pragma unroll
            for (int j=0;j<4;j++) acc[i][j] = fmaf(av[i], bv[j], acc[i][j]);
    }
    #pragma unroll
    for (int i=0;i<4;i++){
        int r = r0 + ty*4 + i;
        int c = c0 + tx*4;
        float4 o = make_float4(acc[i][0]+in_b[c], acc[i][1]+in_b[c+1],
                               acc[i][2]+in_b[c+2], acc[i][3]+in_b[c+3]);
        *(float4*)&g_h[(size_t)r*Hh + c] = o;
    }
}

// ---------------- GEMM2: S[b] = sum_k alpha[b,k] A[k] @ shifted(h[b]) ----------------
// per-b GEMM: M=256(i), Ncols=T*H=32768 (t,h), Kred=K*N=2048
// BM=128, BN=128 (one t per tile), BK=16, 256 threads, 8x8 micro-tile
__global__ void __launch_bounds__(256) gemm2_kernel(){
    __shared__ float Ast[16*132];  // [jj][ii]
    __shared__ float Bs[16*128];   // [jj][cc]
    int bx = blockIdx.x;           // 0..255 column tile
    int i0 = blockIdx.y * 128;     // 0 or 128
    int b  = blockIdx.z;
    int t  = bx >> 1;
    int h0 = (bx & 1) * 128;
    int tid = threadIdx.x;
    int tx = tid & 15, ty = tid >> 4;
    float acc[8][8] = {};
    for (int k=0; k<Kk; k++){
        if (t < k) break;
        float al = g_alpha[b*Kk + k];
        const float* Ab = g_An + (size_t)k*Nn*Nn + (size_t)i0*Nn;
        const float* Bp = g_h + ((size_t)(b*Nn)*Tt + (t-k))*Hh + h0;
        for (int j0=0; j0<Nn; j0+=16){
            #pragma unroll
            for (int l=0;l<8;l++){
                int idx = tid + l*256;
                int jj = idx & 15, ii = idx >> 4;
                Ast[jj*132 + ii] = al * Ab[(size_t)ii*Nn + j0 + jj];
            }
            #pragma unroll
            for (int l=0;l<8;l++){
                int idx = tid + l*256;
                int cc = idx & 127, jj = idx >> 7;
                Bs[jj*128 + cc] = Bp[(size_t)(j0+jj)*(Tt*Hh) + cc];
            }
            __syncthreads();
            #pragma unroll
            for (int kk=0;kk<16;kk++){
                float4 a0 = *(const float4*)&Ast[kk*132 + ty*8];
                float4 a1 = *(const float4*)&Ast[kk*132 + ty*8 + 4];
                float4 b0 = *(const float4*)&Bs[kk*128 + tx*8];
                float4 b1 = *(const float4*)&Bs[kk*128 + tx*8 + 4];
                float av[8]={a0.x,a0.y,a0.z,a0.w,a1.x,a1.y,a1.z,a1.w};
                float bv[8]={b0.x,b0.y,b0.z,b0.w,b1.x,b1.y,b1.z,b1.w};
                #pragma unroll
                for (int i=0;i<8;i++)
                    #pragma unroll
                    for (int j=0;j<8;j++) acc[i][j] = fmaf(av[i], bv[j], acc[i][j]);
            }
            __syncthreads();
        }
    }
    #pragma unroll
    for (int i=0;i<8;i++){
        int gi = i0 + ty*8 + i;
        float* dst = &g_S[((size_t)(b*Nn + gi)*Tt + t)*Hh + h0 + tx*8];
        *(float4*)dst     = make_float4(acc[i][0],acc[i][1],acc[i][2],acc[i][3]);
        *(float4*)(dst+4) = make_float4(acc[i][4],acc[i][5],acc[i][6],acc[i][7]);
    }
}

// ---------------- GEMM3: S @ out_w + out_b + residual, LayerNorm, GELU ----------------
// rows R=131072, Kred=256, cols=256 (full row per block for LN)
// BM=64, BN=256, BK=16, 256 threads: ty->rows (TM=4), tx->cols (TN=16)
__global__ void __launch_bounds__(256) gemm3_kernel(const float* __restrict__ out_w,
                                                    const float* __restrict__ out_b,
                                                    const float* __restrict__ ln_g,
                                                    const float* __restrict__ ln_b,
                                                    float* __restrict__ out){
    __shared__ float Sst[16*68];    // [kk][ii]
    __shared__ float Ws[16*256];    // [kk][cc]; reused as reduction buffer
    __shared__ float mu_s[64], rs_s[64];
    int r0 = blockIdx.x * 64;
    int tid = threadIdx.x;
    int tx = tid & 15, ty = tid >> 4;
    float acc[4][16] = {};
    for (int k0=0;k0<Hh;k0+=16){
        #pragma unroll
        for (int l=0;l<4;l++){
            int idx = tid + l*256;
            int kk = idx & 15, ii = idx >> 4;
            Sst[kk*68 + ii] = g_S[(size_t)(r0+ii)*Hh + k0 + kk];
        }
        #pragma unroll
        for (int l=0;l<16;l++){
            int idx = tid + l*256;
            int cc = idx & 255, kk = idx >> 8;
            Ws[kk*256 + cc] = out_w[(size_t)(k0+kk)*Hh + cc];
        }
        __syncthreads();
        #pragma unroll
        for (int kk=0;kk<16;kk++){
            float4 a = *(const float4*)&Sst[kk*68 + ty*4];
            float av[4]={a.x,a.y,a.z,a.w};
            float wv[16];
            #pragma unroll
            for (int j4=0;j4<4;j4++){
                float4 w = *(const float4*)&Ws[kk*256 + tx*16 + j4*4];
                wv[j4*4]=w.x; wv[j4*4+1]=w.y; wv[j4*4+2]=w.z; wv[j4*4+3]=w.w;
            }
            #pragma unroll
            for (int i=0;i<4;i++)
                #pragma unroll
                for (int j=0;j<16;j++) acc[i][j] = fmaf(av[i], wv[j], acc[i][j]);
        }
        __syncthreads();
    }
    // bias + residual; per-thread partial LN sums
    float psum[4], psq[4];
    #pragma unroll
    for (int i=0;i<4;i++){
        int r = r0 + ty*4 + i;
        psum[i]=0.f; psq[i]=0.f;
        #pragma unroll
        for (int j=0;j<16;j++){
            int c = tx*16 + j;
            float v = acc[i][j] + out_b[c] + g_h[(size_t)r*Hh + c];
            acc[i][j] = v;
            psum[i] += v; psq[i] += v*v;
        }
    }
    float* red = Ws;  // [64][16] sums, +1024 for sq  (last Ws read was before the sync above)
    #pragma unroll
    for (int i=0;i<4;i++){
        red[(ty*4+i)*16 + tx] = psum[i];
        red[1024 + (ty*4+i)*16 + tx] = psq[i];
    }
    __syncthreads();
    if (tid < 64){
        float s=0.f, q=0.f;
        #pragma unroll
        for (int xch=0;xch<16;xch++){ s += red[tid*16+xch]; q += red[1024+tid*16+xch]; }
        float mu = s*(1.0f/Hh);
        float var = q*(1.0f/Hh) - mu*mu;
        mu_s[tid] = mu;
        rs_s[tid] = rsqrtf(var + 1e-5f);
    }
    __syncthreads();
    #pragma unroll
    for (int i=0;i<4;i++){
        int rl = ty*4 + i;
        int r = r0 + rl;
        float mu = mu_s[rl], rs = rs_s[rl];
        #pragma unroll
        for (int j=0;j<16;j++){
            int c = tx*16 + j;
            float v = (acc[i][j] - mu)*rs*ln_g[c] + ln_b[c];
            out[(size_t)r*Hh + c] = gelu_f(v);
        }
    }
}

extern "C" void kernel_launch(void* const* d_in, const int* in_sizes, int n_in,
                              void* d_out, int out_size) {
    const float* x         = (const float*)d_in[0];
    const float* A_list    = (const float*)d_in[1];
    const float* in_w      = (const float*)d_in[2];
    const float* in_b      = (const float*)d_in[3];
    const float* out_w     = (const float*)d_in[4];
    const float* out_b     = (const float*)d_in[5];
    const float* lag_embed = (const float*)d_in[6];
    const float* ctx_w1    = (const float*)d_in[7];
    const float* ctx_b1    = (const float*)d_in[8];
    const float* ctx_w2    = (const float*)d_in[9];
    const float* ctx_b2    = (const float*)d_in[10];
    const float* gate_w1   = (const float*)d_in[11];
    const float* gate_b1   = (const float*)d_in[12];
    const float* gate_w2   = (const float*)d_in[13];
    const float* gate_b2   = (const float*)d_in[14];
    const float* ln_g      = (const float*)d_in[15];
    const float* ln_b      = (const float*)d_in[16];
    float* out = (float*)d_out;

    norm_A_kernel<<<Kk*Nn, 256>>>(A_list);
    ctx1_kernel<<<dim3(64, Bb), 256>>>(x);
    ctx2_kernel<<<Bb, Ff>>>();
    alpha_kernel<<<1, 32>>>(lag_embed, ctx_w1, ctx_b1, ctx_w2, ctx_b2,
                            gate_w1, gate_b1, gate_w2, gate_b2);
    gemm1_kernel<<<dim3(4, RR/64), 256>>>(x, in_w, in_b);
    gemm2_kernel<<<dim3(256, 2, Bb), 256>>>();
    gemm3_kernel<<<RR/64, 256>>>(out_w, out_b, ln_g, ln_b, out);
}

// round 4
// speedup vs baseline: 5.1335x; 5.1335x over previous
#include <cuda_runtime.h>
#include <cuda_bf16.h>
#include <math.h>
#include <stdint.h>

#define Bb 4
#define Nn 256
#define Tt 128
#define Ff 64
#define Kk 8
#define Hh 256
#define Ee 8
#define RR (Bb*Nn*Tt)   /* 131072 rows */

// ---------------- scratch ----------------
__device__ __align__(128) float         g_h[(size_t)RR*Hh];            // fp32 h (residual)
__device__ __align__(128) __nv_bfloat16 g_hbT[(size_t)Bb*Tt*Hh*Nn];    // [b][t][c][n]
__device__ __align__(128) __nv_bfloat16 g_Sb[(size_t)RR*Hh];           // S bf16 rows (b,n,t)
__device__ __align__(128) __nv_bfloat16 g_Abf[(size_t)Bb*Kk*Nn*Nn];    // alpha-scaled A
__device__ __align__(128) __nv_bfloat16 g_owT[Hh*Hh];                  // out_w^T bf16
__device__ __align__(128) float g_An[Kk*Nn*Nn];
__device__ __align__(128) float g_ctxp[Bb*64*Ff];
__device__ __align__(128) float g_ctx[Bb*Ff];
__device__ __align__(128) float g_alpha[Bb*Kk];

__device__ __forceinline__ float gelu_f(float x){
    return 0.5f*x*(1.0f + erff(x*0.7071067811865476f));
}
__device__ __forceinline__ uint32_t smem_u32(const void* p){
    uint32_t a;
    asm("{ .reg .u64 t; cvta.to.shared.u64 t, %1; cvt.u32.u64 %0, t; }" : "=r"(a) : "l"(p));
    return a;
}
__device__ __forceinline__ void cp16(uint32_t dst, const void* src){
    asm volatile("cp.async.cg.shared.global [%0], [%1], 16;" :: "r"(dst), "l"(src) : "memory");
}
__device__ __forceinline__ void cp_commit(){
    asm volatile("cp.async.commit_group;" ::: "memory");
}
__device__ __forceinline__ void cp_wait1(){
    asm volatile("cp.async.wait_group 1;" ::: "memory");
}
__device__ __forceinline__ void cp_wait0(){
    asm volatile("cp.async.wait_group 0;" ::: "memory");
}
__device__ __forceinline__ void ldm4(uint32_t* r, uint32_t addr){
    asm volatile("ldmatrix.sync.aligned.m8n8.x4.shared.b16 {%0,%1,%2,%3}, [%4];"
        : "=r"(r[0]),"=r"(r[1]),"=r"(r[2]),"=r"(r[3]) : "r"(addr));
}
__device__ __forceinline__ void mma16816(float* d, const uint32_t* a, uint32_t b0, uint32_t b1){
    asm volatile("mma.sync.aligned.m16n8k16.row.col.f32.bf16.bf16.f32 "
        "{%0,%1,%2,%3}, {%4,%5,%6,%7}, {%8,%9}, {%0,%1,%2,%3};"
        : "+f"(d[0]),"+f"(d[1]),"+f"(d[2]),"+f"(d[3])
        : "r"(a[0]),"r"(a[1]),"r"(a[2]),"r"(a[3]),"r"(b0),"r"(b1));
}

// ---------------- A normalization ----------------
__global__ void norm_A_kernel(const float* __restrict__ A_list){
    int row = blockIdx.x;
    int j = threadIdx.x;
    float v = A_list[(size_t)row*Nn + j];
    __shared__ float red[256];
    red[j] = v; __syncthreads();
    #pragma unroll
    for (int s=128; s>0; s>>=1){ if (j<s) red[j]+=red[j+s]; __syncthreads(); }
    float denom = fmaxf(red[0], 1e-8f);
    g_An[(size_t)row*Nn + j] = v/denom;
}

// ---------------- ctx mean ----------------
__global__ void ctx1_kernel(const float* __restrict__ x){
    int c = blockIdx.x, b = blockIdx.y;
    int f = threadIdx.x & 63;
    int part = threadIdx.x >> 6;
    const float* xb = x + (size_t)b*Nn*Tt*Ff;
    int start = c*512 + part*128;
    float acc = 0.f;
    for (int nt=start; nt<start+128; nt++) acc += xb[(size_t)nt*Ff + f];
    __shared__ float red[256];
    red[threadIdx.x] = acc; __syncthreads();
    if (part==0)
        g_ctxp[((size_t)b*64 + c)*Ff + f] = red[f]+red[64+f]+red[128+f]+red[192+f];
}
__global__ void ctx2_kernel(){
    int b = blockIdx.x; int f = threadIdx.x;
    float s = 0.f;
    for (int c=0;c<64;c++) s += g_ctxp[((size_t)b*64 + c)*Ff + f];
    g_ctx[b*Ff + f] = s * (1.0f/(Nn*Tt));
}

// ---------------- gating MLP -> alpha ----------------
__global__ void alpha_kernel(const float* __restrict__ lag_embed,
                             const float* __restrict__ ctx_w1, const float* __restrict__ ctx_b1,
                             const float* __restrict__ ctx_w2, const float* __restrict__ ctx_b2,
                             const float* __restrict__ gate_w1, const float* __restrict__ gate_b1,
                             const float* __restrict__ gate_w2, const float* __restrict__ gate_b2){
    int tid = threadIdx.x;
    if (tid >= Bb*Kk) return;
    int b = tid / Kk, k = tid % Kk;
    float t1[Ee];
    #pragma unroll
    for (int e=0;e<Ee;e++){
        float s = ctx_b1[e];
        for (int f=0;f<Ff;f++) s += g_ctx[b*Ff+f]*ctx_w1[f*Ee+e];
        t1[e] = gelu_f(s);
    }
    float cf[Ee];
    #pragma unroll
    for (int e2=0;e2<Ee;e2++){
        float s = ctx_b2[e2];
        for (int e=0;e<Ee;e++) s += t1[e]*ctx_w2[e*Ee+e2];
        cf[e2] = s;
    }
    float gi[2*Ee];
    #pragma unroll
    for (int e=0;e<Ee;e++){ gi[e]=lag_embed[k*Ee+e]; gi[Ee+e]=cf[e]; }
    float g1[Ee];
    #pragma unroll
    for (int e=0;e<Ee;e++){
        float s = gate_b1[e];
        for (int i=0;i<2*Ee;i++) s += gi[i]*gate_w1[i*Ee+e];
        g1[e] = gelu_f(s);
    }
    float s = gate_b2[0];
    #pragma unroll
    for (int e=0;e<Ee;e++) s += g1[e]*gate_w2[e];
    g_alpha[b*Kk + k] = 1.0f/(1.0f + expf(-s));
}

// ---------------- scale A by alpha -> bf16 ----------------
__global__ void scaleA_kernel(){
    int b = blockIdx.y;
    int ki = blockIdx.x;
    int j = threadIdx.x;
    int k = ki >> 8;
    float v = g_alpha[b*Kk + k] * g_An[(size_t)ki*Nn + j];
    g_Abf[((size_t)b*Kk*Nn + ki)*Nn + j] = __float2bfloat16(v);
}

// ---------------- out_w transpose -> bf16 ----------------
__global__ void owT_kernel(const float* __restrict__ out_w){
    int co = blockIdx.x, c = threadIdx.x;
    g_owT[(size_t)co*Hh + c] = __float2bfloat16(out_w[(size_t)c*Hh + co]);
}

// ---------------- GEMM1: h = x @ in_w + in_b (fp32) ----------------
__global__ void __launch_bounds__(256) gemm1_kernel(const float* __restrict__ x,
                                                    const float* __restrict__ in_w,
                                                    const float* __restrict__ in_b){
    __shared__ float Ast[64*68];
    __shared__ float Bs[64*64];
    int r0 = blockIdx.y * 64;
    int c0 = blockIdx.x * 64;
    int tid = threadIdx.x;
    int tx = tid & 15, ty = tid >> 4;
    #pragma unroll
    for (int l=0;l<16;l++){
        int idx = tid + l*256;
        int kk = idx & 63, ii = idx >> 6;
        Ast[kk*68 + ii] = x[(size_t)(r0+ii)*Ff + kk];
    }
    #pragma unroll
    for (int l=0;l<16;l++){
        int idx = tid + l*256;
        int cc = idx & 63, kk = idx >> 6;
        Bs[kk*64 + cc] = in_w[(size_t)kk*Hh + c0 + cc];
    }
    __syncthreads();
    float acc[4][4] = {};
    #pragma unroll 8
    for (int kk=0; kk<64; kk++){
        float4 a = *(const float4*)&Ast[kk*68 + ty*4];
        float4 w = *(const float4*)&Bs[kk*64 + tx*4];
        float av[4]={a.x,a.y,a.z,a.w}, bv[4]={w.x,w.y,w.z,w.w};
        #pragma unroll
        for (int i=0;i<4;i++)
            #pragma unroll
            for (int j=0;j<4;j++) acc[i][j] = fmaf(av[i], bv[j], acc[i][j]);
    }
    #pragma unroll
    for (int i=0;i<4;i++){
        int r = r0 + ty*4 + i;
        int c = c0 + tx*4;
        float4 o = make_float4(acc[i][0]+in_b[c], acc[i][1]+in_b[c+1],
                               acc[i][2]+in_b[c+2], acc[i][3]+in_b[c+3]);
        *(float4*)&g_h[(size_t)r*Hh + c] = o;
    }
}

// ---------------- transpose h -> g_hbT[b][t][c][n] bf16 ----------------
__global__ void __launch_bounds__(256) transpose_kernel(){
    __shared__ float tile[64][65];
    int b = blockIdx.z, t = blockIdx.y;
    int n0 = (blockIdx.x & 3)*64, c0 = (blockIdx.x >> 2)*64;
    int tid = threadIdx.x;
    #pragma unroll
    for (int l=0;l<16;l++){
        int e = tid + l*256;
        int nn = e >> 6, cc = e & 63;
        tile[nn][cc] = g_h[((size_t)(b*Nn + n0+nn)*Tt + t)*Hh + c0 + cc];
    }
    __syncthreads();
    #pragma unroll
    for (int l=0;l<16;l++){
        int e = tid + l*256;
        int cc = e >> 6, nn = e & 63;
        g_hbT[((size_t)(b*Tt + t)*Hh + c0+cc)*Nn + n0+nn] = __float2bfloat16(tile[nn][cc]);
    }
}

// ---------------- GEMM2 (mma.sync bf16) ----------------
// CTA per (quadrant, t, b): D 128x128 = sum_{k,j} Abf[i][j] * hbT[c][j]
// BK=32 (64B per row-chunk), double-buffered cp.async, 80B-pitch smem.
#define PITCH2 80
__global__ void __launch_bounds__(256) gemm2_mma(){
    __shared__ __align__(128) char Asm[2][128*PITCH2];
    __shared__ __align__(128) char Bsm[2][128*PITCH2];
    int tid = threadIdx.x, lane = tid & 31, wid = tid >> 5;
    int q = blockIdx.x, t = blockIdx.y, b = blockIdx.z;
    int i0 = (q >> 1) * 128, c0 = (q & 1) * 128;
    int n_k = min(t+1, Kk);
    int M = n_k * 8;                       // iterations of BK=32 (Nn/32=8 per k)
    int wm = wid >> 2, wn = wid & 3;       // warp tile m64 n32

    int lrow = tid >> 1, lhalf = tid & 1;  // 2 threads/row, 2x16B each = 64B/row
    uint32_t sA0 = smem_u32(&Asm[0][0]), sB0 = smem_u32(&Bsm[0][0]);

    auto issue = [&](int it){
        int k = it >> 3;
        int jb = (it & 7) * 64;            // byte offset of j-chunk in 512B row
        const char* Ab = (const char*)g_Abf
            + (((size_t)(b*Kk + k)*Nn + i0) * Nn) * 2;
        const char* Bp = (const char*)g_hbT
            + (((size_t)(b*Tt + (t-k))*Hh + c0) * Nn) * 2;
        int p = it & 1;
        uint32_t da = sA0 + p*(128*PITCH2) + lrow*PITCH2 + lhalf*32;
        uint32_t db = sB0 + p*(128*PITCH2) + lrow*PITCH2 + lhalf*32;
        const char* ga = Ab + (size_t)lrow*512 + jb + lhalf*32;
        const char* gb = Bp + (size_t)lrow*512 + jb + lhalf*32;
        cp16(da, ga); cp16(da+16, ga+16);
        cp16(db, gb); cp16(db+16, gb+16);
        cp_commit();
    };

    float acc[4][4][4] = {};
    issue(0);
    for (int it=0; it<M; it++){
        int p = it & 1;
        if (it+1 < M){ issue(it+1); cp_wait1(); } else cp_wait0();
        __syncthreads();
        uint32_t baseA = sA0 + p*(128*PITCH2);
        uint32_t baseB = sB0 + p*(128*PITCH2);
        // A x4: [m0k0, m8k0, m0k8, m8k8]
        int arow = ((lane>>3)&1)*8 + (lane&7);
        int akoff = ((lane>>4)&1)*16;
        // B x4: [n0k0, n0k8, n8k0, n8k8]
        int brow = ((lane>>4)&1)*8 + (lane&7);
        int bkoff = ((lane>>3)&1)*16;
        #pragma unroll
        for (int ks=0; ks<2; ks++){
            uint32_t af[4][4];
            #pragma unroll
            for (int mt=0; mt<4; mt++)
                ldm4(af[mt], baseA + (wm*64 + mt*16 + arow)*PITCH2 + akoff + ks*32);
            uint32_t bf[2][4];
            #pragma unroll
            for (int pr=0; pr<2; pr++)
                ldm4(bf[pr], baseB + (wn*32 + pr*16 + brow)*PITCH2 + bkoff + ks*32);
            #pragma unroll
            for (int mt=0; mt<4; mt++)
                #pragma unroll
                for (int nt=0; nt<4; nt++)
                    mma16816(acc[mt][nt], af[mt], bf[nt>>1][(nt&1)*2], bf[nt>>1][(nt&1)*2+1]);
        }
        __syncthreads();
    }

    // epilogue: fp32 acc -> bf16 g_Sb
    #pragma unroll
    for (int mt=0; mt<4; mt++){
        int il = wm*64 + mt*16 + (lane>>2);
        #pragma unroll
        for (int nt=0; nt<4; nt++){
            int col = c0 + wn*32 + nt*8 + (lane&3)*2;
            size_t r_lo = ((size_t)(b*Nn + i0 + il)*Tt + t)*Hh + col;
            size_t r_hi = ((size_t)(b*Nn + i0 + il + 8)*Tt + t)*Hh + col;
            __nv_bfloat162 vlo = __floats2bfloat162_rn(acc[mt][nt][0], acc[mt][nt][1]);
            __nv_bfloat162 vhi = __floats2bfloat162_rn(acc[mt][nt][2], acc[mt][nt][3]);
            *(uint32_t*)&g_Sb[r_lo] = *(uint32_t*)&vlo;
            *(uint32_t*)&g_Sb[r_hi] = *(uint32_t*)&vhi;
        }
    }
}

// ---------------- GEMM3 (mma.sync bf16) + bias + residual + LN + GELU ----------------
// CTA: 64 rows x 256 cols, Kred=256, BK=64 single-buffered.
// dyn smem 46080B: A 64x144 @0, B 256x144 @9216; red[64][8] reuses A region after loop.
#define PITCH3 144
__global__ void __launch_bounds__(256) gemm3_mma(const float* __restrict__ out_b,
                                                 const float* __restrict__ ln_g,
                                                 const float* __restrict__ ln_b,
                                                 float* __restrict__ out){
    extern __shared__ char dsm[];
    uint32_t sA = smem_u32(dsm);
    uint32_t sB = sA + 64*PITCH3;
    float* red = (float*)dsm;                       // [64][8] after mainloop
    int tid = threadIdx.x, lane = tid & 31, wid = tid >> 5;
    int r0 = blockIdx.x * 64;
    int wm = wid >> 2, wn = wid & 3;                // warp tile m32 n64

    float acc[2][8][4] = {};
    const char* Abase = (const char*)g_Sb + (size_t)r0*Hh*2;
    const char* Bbase = (const char*)g_owT;

    for (int kc=0; kc<4; kc++){
        __syncthreads();
        // A: 64 rows x 128B = 512 chunks; 2 per thread
        #pragma unroll
        for (int u=0; u<2; u++){
            int e = u*256 + tid;
            int row = e >> 3, ch = e & 7;
            cp16(sA + row*PITCH3 + ch*16, Abase + (size_t)row*512 + kc*128 + ch*16);
        }
        // B: 256 rows x 128B = 2048 chunks; 8 per thread
        #pragma unroll
        for (int u=0; u<8; u++){
            int e = u*256 + tid;
            int row = e >> 3, ch = e & 7;
            cp16(sB + row*PITCH3 + ch*16, Bbase + (size_t)row*512 + kc*128 + ch*16);
        }
        cp_commit(); cp_wait0();
        __syncthreads();
        int arow = ((lane>>3)&1)*8 + (lane&7);
        int akoff = ((lane>>4)&1)*16;
        int brow = ((lane>>4)&1)*8 + (lane&7);
        int bkoff = ((lane>>3)&1)*16;
        #pragma unroll
        for (int ks=0; ks<4; ks++){
            uint32_t af[2][4];
            #pragma unroll
            for (int mt=0; mt<2; mt++)
                ldm4(af[mt], sA + (wm*32 + mt*16 + arow)*PITCH3 + akoff + ks*32);
            uint32_t bfv[4][4];
            #pragma unroll
            for (int pr=0; pr<4; pr++)
                ldm4(bfv[pr], sB + (wn*64 + pr*16 + brow)*PITCH3 + bkoff + ks*32);
            #pragma unroll
            for (int mt=0; mt<2; mt++)
                #pragma unroll
                for (int nt=0; nt<8; nt++)
                    mma16816(acc[mt][nt], af[mt], bfv[nt>>1][(nt&1)*2], bfv[nt>>1][(nt&1)*2+1]);
        }
    }
    __syncthreads();

    // pass 1: bias + residual in place; per-row partial sums -> smem red
    #pragma unroll
    for (int mt=0; mt<2; mt++){
        #pragma unroll
        for (int half=0; half<2; half++){
            int rl = wm*32 + mt*16 + half*8 + (lane>>2);
            int r = r0 + rl;
            float s = 0.f, qd = 0.f;
            #pragma unroll
            for (int nt=0; nt<8; nt++){
                int c = wn*64 + nt*8 + (lane&3)*2;
                float v0 = acc[mt][nt][half*2]   + out_b[c]   + g_h[(size_t)r*Hh + c];
                float v1 = acc[mt][nt][half*2+1] + out_b[c+1] + g_h[(size_t)r*Hh + c+1];
                acc[mt][nt][half*2]   = v0;
                acc[mt][nt][half*2+1] = v1;
                s += v0 + v1; qd += v0*v0 + v1*v1;
            }
            s  += __shfl_xor_sync(0xFFFFFFFF, s, 1);  s  += __shfl_xor_sync(0xFFFFFFFF, s, 2);
            qd += __shfl_xor_sync(0xFFFFFFFF, qd, 1); qd += __shfl_xor_sync(0xFFFFFFFF, qd, 2);
            if ((lane & 3) == 0){
                red[rl*8 + wn]     = s;
                red[rl*8 + 4 + wn] = qd;
            }
        }
    }
    __syncthreads();
    // pass 2: normalize + gelu + store
    #pragma unroll
    for (int mt=0; mt<2; mt++){
        #pragma unroll
        for (int half=0; half<2; half++){
            int rl = wm*32 + mt*16 + half*8 + (lane>>2);
            int r = r0 + rl;
            float s  = red[rl*8+0] + red[rl*8+1] + red[rl*8+2] + red[rl*8+3];
            float qd = red[rl*8+4] + red[rl*8+5] + red[rl*8+6] + red[rl*8+7];
            float mu = s * (1.0f/Hh);
            float rs = rsqrtf(qd*(1.0f/Hh) - mu*mu + 1e-5f);
            #pragma unroll
            for (int nt=0; nt<8; nt++){
                int c = wn*64 + nt*8 + (lane&3)*2;
                float v0 = acc[mt][nt][half*2];
                float v1 = acc[mt][nt][half*2+1];
                float o0 = gelu_f((v0 - mu)*rs*ln_g[c]   + ln_b[c]);
                float o1 = gelu_f((v1 - mu)*rs*ln_g[c+1] + ln_b[c+1]);
                float2 o = make_float2(o0, o1);
                *(float2*)&out[(size_t)r*Hh + c] = o;
            }
        }
    }
}

extern "C" void kernel_launch(void* const* d_in, const int* in_sizes, int n_in,
                              void* d_out, int out_size) {
    const float* x         = (const float*)d_in[0];
    const float* A_list    = (const float*)d_in[1];
    const float* in_w      = (const float*)d_in[2];
    const float* in_b      = (const float*)d_in[3];
    const float* out_w     = (const float*)d_in[4];
    const float* out_b     = (const float*)d_in[5];
    const float* lag_embed = (const float*)d_in[6];
    const float* ctx_w1    = (const float*)d_in[7];
    const float* ctx_b1    = (const float*)d_in[8];
    const float* ctx_w2    = (const float*)d_in[9];
    const float* ctx_b2    = (const float*)d_in[10];
    const float* gate_w1   = (const float*)d_in[11];
    const float* gate_b1   = (const float*)d_in[12];
    const float* gate_w2   = (const float*)d_in[13];
    const float* gate_b2   = (const float*)d_in[14];
    const float* ln_g      = (const float*)d_in[15];
    const float* ln_b      = (const float*)d_in[16];
    float* out = (float*)d_out;

    norm_A_kernel<<<Kk*Nn, 256>>>(A_list);
    ctx1_kernel<<<dim3(64, Bb), 256>>>(x);
    ctx2_kernel<<<Bb, Ff>>>();
    alpha_kernel<<<1, 32>>>(lag_embed, ctx_w1, ctx_b1, ctx_w2, ctx_b2,
                            gate_w1, gate_b1, gate_w2, gate_b2);
    scaleA_kernel<<<dim3(Kk*Nn, Bb), 256>>>();
    gemm1_kernel<<<dim3(4, RR/64), 256>>>(x, in_w, in_b);
    transpose_kernel<<<dim3(16, Tt, Bb), 256>>>();
    owT_kernel<<<Hh, Hh>>>(out_w);
    gemm2_mma<<<dim3(4, Tt, Bb), 256>>>();
    gemm3_mma<<<RR/64, 256, 46080>>>(out_b, ln_g, ln_b, out);
}

// round 5
// speedup vs baseline: 5.1337x; 1.0000x over previous
#include <cuda_runtime.h>
#include <cuda_bf16.h>
#include <math.h>
#include <stdint.h>

#define Bb 4
#define Nn 256
#define Tt 128
#define Ff 64
#define Kk 8
#define Hh 256
#define Ee 8
#define RR (Bb*Nn*Tt)   /* 131072 rows */

// ---------------- scratch ----------------
__device__ __align__(128) float         g_h[(size_t)RR*Hh];            // fp32 h (residual)
__device__ __align__(128) __nv_bfloat16 g_hbT[(size_t)Bb*Tt*Hh*Nn];    // [b][t][c][n]
__device__ __align__(128) __nv_bfloat16 g_Sb[(size_t)RR*Hh];           // S bf16 rows (b,n,t)
__device__ __align__(128) __nv_bfloat16 g_Abf[(size_t)Bb*Kk*Nn*Nn];    // alpha-scaled A
__device__ __align__(128) __nv_bfloat16 g_owT[Hh*Hh];                  // out_w^T bf16
__device__ __align__(128) float g_An[Kk*Nn*Nn];
__device__ __align__(128) float g_ctxp[Bb*64*Ff];
__device__ __align__(128) float g_ctx[Bb*Ff];
__device__ __align__(128) float g_alpha[Bb*Kk];

__device__ __forceinline__ float gelu_f(float x){
    return 0.5f*x*(1.0f + erff(x*0.7071067811865476f));
}
__device__ __forceinline__ uint32_t smem_u32(const void* p){
    uint32_t a;
    asm("{ .reg .u64 t; cvta.to.shared.u64 t, %1; cvt.u32.u64 %0, t; }" : "=r"(a) : "l"(p));
    return a;
}
__device__ __forceinline__ void cp16(uint32_t dst, const void* src){
    asm volatile("cp.async.cg.shared.global [%0], [%1], 16;" :: "r"(dst), "l"(src) : "memory");
}
__device__ __forceinline__ void cp_commit(){
    asm volatile("cp.async.commit_group;" ::: "memory");
}
__device__ __forceinline__ void cp_wait1(){
    asm volatile("cp.async.wait_group 1;" ::: "memory");
}
__device__ __forceinline__ void cp_wait0(){
    asm volatile("cp.async.wait_group 0;" ::: "memory");
}
__device__ __forceinline__ void ldm4(uint32_t* r, uint32_t addr){
    asm volatile("ldmatrix.sync.aligned.m8n8.x4.shared.b16 {%0,%1,%2,%3}, [%4];"
        : "=r"(r[0]),"=r"(r[1]),"=r"(r[2]),"=r"(r[3]) : "r"(addr));
}
__device__ __forceinline__ void mma16816(float* d, const uint32_t* a, uint32_t b0, uint32_t b1){
    asm volatile("mma.sync.aligned.m16n8k16.row.col.f32.bf16.bf16.f32 "
        "{%0,%1,%2,%3}, {%4,%5,%6,%7}, {%8,%9}, {%0,%1,%2,%3};"
        : "+f"(d[0]),"+f"(d[1]),"+f"(d[2]),"+f"(d[3])
        : "r"(a[0]),"r"(a[1]),"r"(a[2]),"r"(a[3]),"r"(b0),"r"(b1));
}

// ---------------- A normalization ----------------
__global__ void norm_A_kernel(const float* __restrict__ A_list){
    int row = blockIdx.x;
    int j = threadIdx.x;
    float v = A_list[(size_t)row*Nn + j];
    __shared__ float red[256];
    red[j] = v; __syncthreads();
    #pragma unroll
    for (int s=128; s>0; s>>=1){ if (j<s) red[j]+=red[j+s]; __syncthreads(); }
    float denom = fmaxf(red[0], 1e-8f);
    g_An[(size_t)row*Nn + j] = v/denom;
}

// ---------------- ctx mean ----------------
__global__ void ctx1_kernel(const float* __restrict__ x){
    int c = blockIdx.x, b = blockIdx.y;
    int f = threadIdx.x & 63;
    int part = threadIdx.x >> 6;
    const float* xb = x + (size_t)b*Nn*Tt*Ff;
    int start = c*512 + part*128;
    float acc = 0.f;
    for (int nt=start; nt<start+128; nt++) acc += xb[(size_t)nt*Ff + f];
    __shared__ float red[256];
    red[threadIdx.x] = acc; __syncthreads();
    if (part==0)
        g_ctxp[((size_t)b*64 + c)*Ff + f] = red[f]+red[64+f]+red[128+f]+red[192+f];
}
__global__ void ctx2_kernel(){
    int b = blockIdx.x; int f = threadIdx.x;
    float s = 0.f;
    for (int c=0;c<64;c++) s += g_ctxp[((size_t)b*64 + c)*Ff + f];
    g_ctx[b*Ff + f] = s * (1.0f/(Nn*Tt));
}

// ---------------- gating MLP -> alpha ----------------
__global__ void alpha_kernel(const float* __restrict__ lag_embed,
                             const float* __restrict__ ctx_w1, const float* __restrict__ ctx_b1,
                             const float* __restrict__ ctx_w2, const float* __restrict__ ctx_b2,
                             const float* __restrict__ gate_w1, const float* __restrict__ gate_b1,
                             const float* __restrict__ gate_w2, const float* __restrict__ gate_b2){
    int tid = threadIdx.x;
    if (tid >= Bb*Kk) return;
    int b = tid / Kk, k = tid % Kk;
    float t1[Ee];
    #pragma unroll
    for (int e=0;e<Ee;e++){
        float s = ctx_b1[e];
        for (int f=0;f<Ff;f++) s += g_ctx[b*Ff+f]*ctx_w1[f*Ee+e];
        t1[e] = gelu_f(s);
    }
    float cf[Ee];
    #pragma unroll
    for (int e2=0;e2<Ee;e2++){
        float s = ctx_b2[e2];
        for (int e=0;e<Ee;e++) s += t1[e]*ctx_w2[e*Ee+e2];
        cf[e2] = s;
    }
    float gi[2*Ee];
    #pragma unroll
    for (int e=0;e<Ee;e++){ gi[e]=lag_embed[k*Ee+e]; gi[Ee+e]=cf[e]; }
    float g1[Ee];
    #pragma unroll
    for (int e=0;e<Ee;e++){
        float s = gate_b1[e];
        for (int i=0;i<2*Ee;i++) s += gi[i]*gate_w1[i*Ee+e];
        g1[e] = gelu_f(s);
    }
    float s = gate_b2[0];
    #pragma unroll
    for (int e=0;e<Ee;e++) s += g1[e]*gate_w2[e];
    g_alpha[b*Kk + k] = 1.0f/(1.0f + expf(-s));
}

// ---------------- scale A by alpha -> bf16 ----------------
__global__ void scaleA_kernel(){
    int b = blockIdx.y;
    int ki = blockIdx.x;
    int j = threadIdx.x;
    int k = ki >> 8;
    float v = g_alpha[b*Kk + k] * g_An[(size_t)ki*Nn + j];
    g_Abf[((size_t)b*Kk*Nn + ki)*Nn + j] = __float2bfloat16(v);
}

// ---------------- out_w transpose -> bf16 ----------------
__global__ void owT_kernel(const float* __restrict__ out_w){
    int co = blockIdx.x, c = threadIdx.x;
    g_owT[(size_t)co*Hh + c] = __float2bfloat16(out_w[(size_t)c*Hh + co]);
}

// ---------------- GEMM1: h = x @ in_w + in_b (fp32) ----------------
__global__ void __launch_bounds__(256) gemm1_kernel(const float* __restrict__ x,
                                                    const float* __restrict__ in_w,
                                                    const float* __restrict__ in_b){
    __shared__ float Ast[64*68];
    __shared__ float Bs[64*64];
    int r0 = blockIdx.y * 64;
    int c0 = blockIdx.x * 64;
    int tid = threadIdx.x;
    int tx = tid & 15, ty = tid >> 4;
    #pragma unroll
    for (int l=0;l<16;l++){
        int idx = tid + l*256;
        int kk = idx & 63, ii = idx >> 6;
        Ast[kk*68 + ii] = x[(size_t)(r0+ii)*Ff + kk];
    }
    #pragma unroll
    for (int l=0;l<16;l++){
        int idx = tid + l*256;
        int cc = idx & 63, kk = idx >> 6;
        Bs[kk*64 + cc] = in_w[(size_t)kk*Hh + c0 + cc];
    }
    __syncthreads();
    float acc[4][4] = {};
    #pragma unroll 8
    for (int kk=0; kk<64; kk++){
        float4 a = *(const float4*)&Ast[kk*68 + ty*4];
        float4 w = *(const float4*)&Bs[kk*64 + tx*4];
        float av[4]={a.x,a.y,a.z,a.w}, bv[4]={w.x,w.y,w.z,w.w};
        #pragma unroll
        for (int i=0;i<4;i++)
            #pragma unroll
            for (int j=0;j<4;j++) acc[i][j] = fmaf(av[i], bv[j], acc[i][j]);
    }
    #pragma unroll
    for (int i=0;i<4;i++){
        int r = r0 + ty*4 + i;
        int c = c0 + tx*4;
        float4 o = make_float4(acc[i][0]+in_b[c], acc[i][1]+in_b[c+1],
                               acc[i][2]+in_b[c+2], acc[i][3]+in_b[c+3]);
        *(float4*)&g_h[(size_t)r*Hh + c] = o;
    }
}

// ---------------- transpose h -> g_hbT[b][t][c][n] bf16 ----------------
__global__ void __launch_bounds__(256) transpose_kernel(){
    __shared__ float tile[64][65];
    int b = blockIdx.z, t = blockIdx.y;
    int n0 = (blockIdx.x & 3)*64, c0 = (blockIdx.x >> 2)*64;
    int tid = threadIdx.x;
    #pragma unroll
    for (int l=0;l<16;l++){
        int e = tid + l*256;
        int nn = e >> 6, cc = e & 63;
        tile[nn][cc] = g_h[((size_t)(b*Nn + n0+nn)*Tt + t)*Hh + c0 + cc];
    }
    __syncthreads();
    #pragma unroll
    for (int l=0;l<16;l++){
        int e = tid + l*256;
        int cc = e >> 6, nn = e & 63;
        g_hbT[((size_t)(b*Tt + t)*Hh + c0+cc)*Nn + n0+nn] = __float2bfloat16(tile[nn][cc]);
    }
}

// ---------------- GEMM2 (mma.sync bf16) ----------------
// CTA per (quadrant, t, b): D 128x128 = sum_{k,j} Abf[i][j] * hbT[c][j]
// BK=32 (64B per row-chunk), double-buffered cp.async, 80B-pitch smem.
#define PITCH2 80
__global__ void __launch_bounds__(256) gemm2_mma(){
    __shared__ __align__(128) char Asm[2][128*PITCH2];
    __shared__ __align__(128) char Bsm[2][128*PITCH2];
    int tid = threadIdx.x, lane = tid & 31, wid = tid >> 5;
    int q = blockIdx.x, t = blockIdx.y, b = blockIdx.z;
    int i0 = (q >> 1) * 128, c0 = (q & 1) * 128;
    int n_k = min(t+1, Kk);
    int M = n_k * 8;                       // iterations of BK=32 (Nn/32=8 per k)
    int wm = wid >> 2, wn = wid & 3;       // warp tile m64 n32

    int lrow = tid >> 1, lhalf = tid & 1;  // 2 threads/row, 2x16B each = 64B/row
    uint32_t sA0 = smem_u32(&Asm[0][0]), sB0 = smem_u32(&Bsm[0][0]);

    auto issue = [&](int it){
        int k = it >> 3;
        int jb = (it & 7) * 64;            // byte offset of j-chunk in 512B row
        const char* Ab = (const char*)g_Abf
            + (((size_t)(b*Kk + k)*Nn + i0) * Nn) * 2;
        const char* Bp = (const char*)g_hbT
            + (((size_t)(b*Tt + (t-k))*Hh + c0) * Nn) * 2;
        int p = it & 1;
        uint32_t da = sA0 + p*(128*PITCH2) + lrow*PITCH2 + lhalf*32;
        uint32_t db = sB0 + p*(128*PITCH2) + lrow*PITCH2 + lhalf*32;
        const char* ga = Ab + (size_t)lrow*512 + jb + lhalf*32;
        const char* gb = Bp + (size_t)lrow*512 + jb + lhalf*32;
        cp16(da, ga); cp16(da+16, ga+16);
        cp16(db, gb); cp16(db+16, gb+16);
        cp_commit();
    };

    float acc[4][4][4] = {};
    issue(0);
    for (int it=0; it<M; it++){
        int p = it & 1;
        if (it+1 < M){ issue(it+1); cp_wait1(); } else cp_wait0();
        __syncthreads();
        uint32_t baseA = sA0 + p*(128*PITCH2);
        uint32_t baseB = sB0 + p*(128*PITCH2);
        // A x4: [m0k0, m8k0, m0k8, m8k8]
        int arow = ((lane>>3)&1)*8 + (lane&7);
        int akoff = ((lane>>4)&1)*16;
        // B x4: [n0k0, n0k8, n8k0, n8k8]
        int brow = ((lane>>4)&1)*8 + (lane&7);
        int bkoff = ((lane>>3)&1)*16;
        #pragma unroll
        for (int ks=0; ks<2; ks++){
            uint32_t af[4][4];
            #pragma unroll
            for (int mt=0; mt<4; mt++)
                ldm4(af[mt], baseA + (wm*64 + mt*16 + arow)*PITCH2 + akoff + ks*32);
            uint32_t bf[2][4];
            #pragma unroll
            for (int pr=0; pr<2; pr++)
                ldm4(bf[pr], baseB + (wn*32 + pr*16 + brow)*PITCH2 + bkoff + ks*32);
            #pragma unroll
            for (int mt=0; mt<4; mt++)
                #pragma unroll
                for (int nt=0; nt<4; nt++)
                    mma16816(acc[mt][nt], af[mt], bf[nt>>1][(nt&1)*2], bf[nt>>1][(nt&1)*2+1]);
        }
        __syncthreads();
    }

    // epilogue: fp32 acc -> bf16 g_Sb
    #pragma unroll
    for (int mt=0; mt<4; mt++){
        int il = wm*64 + mt*16 + (lane>>2);
        #pragma unroll
        for (int nt=0; nt<4; nt++){
            int col = c0 + wn*32 + nt*8 + (lane&3)*2;
            size_t r_lo = ((size_t)(b*Nn + i0 + il)*Tt + t)*Hh + col;
            size_t r_hi = ((size_t)(b*Nn + i0 + il + 8)*Tt + t)*Hh + col;
            __nv_bfloat162 vlo = __floats2bfloat162_rn(acc[mt][nt][0], acc[mt][nt][1]);
            __nv_bfloat162 vhi = __floats2bfloat162_rn(acc[mt][nt][2], acc[mt][nt][3]);
            *(uint32_t*)&g_Sb[r_lo] = *(uint32_t*)&vlo;
            *(uint32_t*)&g_Sb[r_hi] = *(uint32_t*)&vhi;
        }
    }
}

// ---------------- GEMM3 (mma.sync bf16) + bias + residual + LN + GELU ----------------
// CTA: 64 rows x 256 cols, Kred=256, BK=64 single-buffered.
// dyn smem 46080B: A 64x144 @0, B 256x144 @9216; red[64][8] reuses A region after loop.
#define PITCH3 144
__global__ void __launch_bounds__(256) gemm3_mma(const float* __restrict__ out_b,
                                                 const float* __restrict__ ln_g,
                                                 const float* __restrict__ ln_b,
                                                 float* __restrict__ out){
    extern __shared__ char dsm[];
    uint32_t sA = smem_u32(dsm);
    uint32_t sB = sA + 64*PITCH3;
    float* red = (float*)dsm;                       // [64][8] after mainloop
    int tid = threadIdx.x, lane = tid & 31, wid = tid >> 5;
    int r0 = blockIdx.x * 64;
    int wm = wid >> 2, wn = wid & 3;                // warp tile m32 n64

    float acc[2][8][4] = {};
    const char* Abase = (const char*)g_Sb + (size_t)r0*Hh*2;
    const char* Bbase = (const char*)g_owT;

    for (int kc=0; kc<4; kc++){
        __syncthreads();
        // A: 64 rows x 128B = 512 chunks; 2 per thread
        #pragma unroll
        for (int u=0; u<2; u++){
            int e = u*256 + tid;
            int row = e >> 3, ch = e & 7;
            cp16(sA + row*PITCH3 + ch*16, Abase + (size_t)row*512 + kc*128 + ch*16);
        }
        // B: 256 rows x 128B = 2048 chunks; 8 per thread
        #pragma unroll
        for (int u=0; u<8; u++){
            int e = u*256 + tid;
            int row = e >> 3, ch = e & 7;
            cp16(sB + row*PITCH3 + ch*16, Bbase + (size_t)row*512 + kc*128 + ch*16);
        }
        cp_commit(); cp_wait0();
        __syncthreads();
        int arow = ((lane>>3)&1)*8 + (lane&7);
        int akoff = ((lane>>4)&1)*16;
        int brow = ((lane>>4)&1)*8 + (lane&7);
        int bkoff = ((lane>>3)&1)*16;
        #pragma unroll
        for (int ks=0; ks<4; ks++){
            uint32_t af[2][4];
            #pragma unroll
            for (int mt=0; mt<2; mt++)
                ldm4(af[mt], sA + (wm*32 + mt*16 + arow)*PITCH3 + akoff + ks*32);
            uint32_t bfv[4][4];
            #pragma unroll
            for (int pr=0; pr<4; pr++)
                ldm4(bfv[pr], sB + (wn*64 + pr*16 + brow)*PITCH3 + bkoff + ks*32);
            #pragma unroll
            for (int mt=0; mt<2; mt++)
                #pragma unroll
                for (int nt=0; nt<8; nt++)
                    mma16816(acc[mt][nt], af[mt], bfv[nt>>1][(nt&1)*2], bfv[nt>>1][(nt&1)*2+1]);
        }
    }
    __syncthreads();

    // pass 1: bias + residual in place; per-row partial sums -> smem red
    #pragma unroll
    for (int mt=0; mt<2; mt++){
        #pragma unroll
        for (int half=0; half<2; half++){
            int rl = wm*32 + mt*16 + half*8 + (lane>>2);
            int r = r0 + rl;
            float s = 0.f, qd = 0.f;
            #pragma unroll
            for (int nt=0; nt<8; nt++){
                int c = wn*64 + nt*8 + (lane&3)*2;
                float v0 = acc[mt][nt][half*2]   + out_b[c]   + g_h[(size_t)r*Hh + c];
                float v1 = acc[mt][nt][half*2+1] + out_b[c+1] + g_h[(size_t)r*Hh + c+1];
                acc[mt][nt][half*2]   = v0;
                acc[mt][nt][half*2+1] = v1;
                s += v0 + v1; qd += v0*v0 + v1*v1;
            }
            s  += __shfl_xor_sync(0xFFFFFFFF, s, 1);  s  += __shfl_xor_sync(0xFFFFFFFF, s, 2);
            qd += __shfl_xor_sync(0xFFFFFFFF, qd, 1); qd += __shfl_xor_sync(0xFFFFFFFF, qd, 2);
            if ((lane & 3) == 0){
                red[rl*8 + wn]     = s;
                red[rl*8 + 4 + wn] = qd;
            }
        }
    }
    __syncthreads();
    // pass 2: normalize + gelu + store
    #pragma unroll
    for (int mt=0; mt<2; mt++){
        #pragma unroll
        for (int half=0; half<2; half++){
            int rl = wm*32 + mt*16 + half*8 + (lane>>2);
            int r = r0 + rl;
            float s  = red[rl*8+0] + red[rl*8+1] + red[rl*8+2] + red[rl*8+3];
            float qd = red[rl*8+4] + red[rl*8+5] + red[rl*8+6] + red[rl*8+7];
            float mu = s * (1.0f/Hh);
            float rs = rsqrtf(qd*(1.0f/Hh) - mu*mu + 1e-5f);
            #pragma unroll
            for (int nt=0; nt<8; nt++){
                int c = wn*64 + nt*8 + (lane&3)*2;
                float v0 = acc[mt][nt][half*2];
                float v1 = acc[mt][nt][half*2+1];
                float o0 = gelu_f((v0 - mu)*rs*ln_g[c]   + ln_b[c]);
                float o1 = gelu_f((v1 - mu)*rs*ln_g[c+1] + ln_b[c+1]);
                float2 o = make_float2(o0, o1);
                *(float2*)&out[(size_t)r*Hh + c] = o;
            }
        }
    }
}

extern "C" void kernel_launch(void* const* d_in, const int* in_sizes, int n_in,
                              void* d_out, int out_size) {
    const float* x         = (const float*)d_in[0];
    const float* A_list    = (const float*)d_in[1];
    const float* in_w      = (const float*)d_in[2];
    const float* in_b      = (const float*)d_in[3];
    const float* out_w     = (const float*)d_in[4];
    const float* out_b     = (const float*)d_in[5];
    const float* lag_embed = (const float*)d_in[6];
    const float* ctx_w1    = (const float*)d_in[7];
    const float* ctx_b1    = (const float*)d_in[8];
    const float* ctx_w2    = (const float*)d_in[9];
    const float* ctx_b2    = (const float*)d_in[10];
    const float* gate_w1   = (const float*)d_in[11];
    const float* gate_b1   = (const float*)d_in[12];
    const float* gate_w2   = (const float*)d_in[13];
    const float* gate_b2   = (const float*)d_in[14];
    const float* ln_g      = (const float*)d_in[15];
    const float* ln_b      = (const float*)d_in[16];
    float* out = (float*)d_out;

    norm_A_kernel<<<Kk*Nn, 256>>>(A_list);
    ctx1_kernel<<<dim3(64, Bb), 256>>>(x);
    ctx2_kernel<<<Bb, Ff>>>();
    alpha_kernel<<<1, 32>>>(lag_embed, ctx_w1, ctx_b1, ctx_w2, ctx_b2,
                            gate_w1, gate_b1, gate_w2, gate_b2);
    scaleA_kernel<<<dim3(Kk*Nn, Bb), 256>>>();
    gemm1_kernel<<<dim3(4, RR/64), 256>>>(x, in_w, in_b);
    transpose_kernel<<<dim3(16, Tt, Bb), 256>>>();
    owT_kernel<<<Hh, Hh>>>(out_w);
    gemm2_mma<<<dim3(4, Tt, Bb), 256>>>();
    gemm3_mma<<<RR/64, 256, 46080>>>(out_b, ln_g, ln_b, out);
}